// round 2
// baseline (speedup 1.0000x reference)
#include <cuda_runtime.h>
#include <cstdint>

// Problem constants (fixed by the dataset)
#define NMAX 100000
#define EMAX 1600000
#define HDIM 128

// ---------------- scratch (device globals; no allocations allowed) ----------
__device__ float g_T[NMAX * HDIM];   // t = h @ W (pre-aggregation)
__device__ float g_A[NMAX * HDIM];   // ping
__device__ float g_B[NMAX * HDIM];   // pong
__device__ float g_deg[NMAX];
__device__ float g_dinv[NMAX];
__device__ float g_selfc[NMAX];      // dinv^2 = 1/deg  (self-loop coefficient)
__device__ int   g_src[EMAX];
__device__ int   g_dst[EMAX];
__device__ float g_coef[EMAX];
__device__ int   g_edge64;           // 1 if edge_index is int64, else int32
__device__ int   g_batch64;          // same for batch

// ---------------- dtype detection (int64 vs int32 index buffers) ------------
// Reading as int32 is always in-bounds for <= element_count elements under
// either interpretation. int64 little-endian data has zero high words.
__global__ void detect_kernel(const int* __restrict__ ei32,
                              const int* __restrict__ b32, int nb) {
    if (blockIdx.x != 0 || threadIdx.x != 0) return;
    int nz = 0;
#pragma unroll
    for (int i = 1; i < 17; i += 2) nz |= ei32[i];       // head: edges are random, nonzero
    g_edge64 = (nz == 0) ? 1 : 0;
    nz = 0;
    for (int k = 0; k < 16; k++) {                        // tail: sorted batch ends ~255
        int j = nb - 1 - k;
        if (j >= 1 && (j & 1)) nz |= b32[j];
    }
    g_batch64 = (nz == 0) ? 1 : 0;
}

// ---------------- graph prep ------------------------------------------------
__global__ void deg_init_kernel(int n) {
    int i = blockIdx.x * blockDim.x + threadIdx.x;
    if (i < n) g_deg[i] = 1.0f;                           // self-loop
}

__global__ void edge_prep_kernel(const void* __restrict__ ei, int E) {
    int e = blockIdx.x * blockDim.x + threadIdx.x;
    if (e >= E) return;
    int s, d;
    if (g_edge64) {
        const long long* p = (const long long*)ei;
        s = (int)p[e]; d = (int)p[E + e];
    } else {
        const int* p = (const int*)ei;
        s = p[e]; d = p[E + e];
    }
    g_src[e] = s;
    g_dst[e] = d;
    atomicAdd(&g_deg[d], 1.0f);
}

__global__ void dinv_kernel(int n) {
    int i = blockIdx.x * blockDim.x + threadIdx.x;
    if (i >= n) return;
    float dv = rsqrtf(g_deg[i]);
    g_dinv[i] = dv;
    g_selfc[i] = dv * dv;
}

__global__ void coef_kernel(int E) {
    int e = blockIdx.x * blockDim.x + threadIdx.x;
    if (e >= E) return;
    g_coef[e] = g_dinv[g_src[e]] * g_dinv[g_dst[e]];
}

// ---------------- layer 1: [N,4] @ [4,128], fused self-loop + bias ----------
__global__ void mm4_kernel(const float* __restrict__ x, const float* __restrict__ W,
                           const float* __restrict__ b,
                           float* __restrict__ T, float* __restrict__ Hout, int n) {
    __shared__ float Ws[4 * 128 + 128];
    for (int i = threadIdx.x; i < 512; i += blockDim.x) Ws[i] = W[i];
    for (int i = threadIdx.x; i < 128; i += blockDim.x) Ws[512 + i] = b[i];
    __syncthreads();
    int node = blockIdx.x * 2 + (threadIdx.x >> 7);
    if (node >= n) return;
    int f = threadIdx.x & 127;
    float4 xv = ((const float4*)x)[node];                 // 16B broadcast per half-block
    float acc = xv.x * Ws[f] + xv.y * Ws[128 + f] + xv.z * Ws[256 + f] + xv.w * Ws[384 + f];
    T[(size_t)node * 128 + f] = acc;
    Hout[(size_t)node * 128 + f] = acc * g_selfc[node] + Ws[512 + f];
}

// ---------------- layers 2..4: [N,128] @ [128,128] --------------------------
// blockDim 256 (8 warps); each warp computes 4 rows x 128 cols.
// W lives in 64KB dynamic smem as float4; per k: 1 LDS.128 + 4 shfl + 16 FFMA.
__global__ void mm128_kernel(const float* __restrict__ Hin, const float* __restrict__ W,
                             const float* __restrict__ b,
                             float* __restrict__ T, float* __restrict__ Hout,
                             int n, int relu_in) {
    extern __shared__ float4 Ws4[];                       // [128][32] float4 = 64KB
    const float4* W4 = (const float4*)W;
    for (int i = threadIdx.x; i < 128 * 32; i += blockDim.x) Ws4[i] = W4[i];
    __syncthreads();

    int warp = threadIdx.x >> 5;
    int lane = threadIdx.x & 31;
    int row0 = (blockIdx.x * 8 + warp) * 4;
    if (row0 >= n) return;

    float4 acc[4];
#pragma unroll
    for (int j = 0; j < 4; j++) acc[j] = make_float4(0.f, 0.f, 0.f, 0.f);

#pragma unroll
    for (int kc = 0; kc < 4; kc++) {
        float h[4];
#pragma unroll
        for (int j = 0; j < 4; j++) {
            int r = row0 + j; if (r >= n) r = n - 1;      // clamp (n % 4 == 0 in practice)
            float v = Hin[(size_t)r * 128 + kc * 32 + lane];
            h[j] = relu_in ? fmaxf(v, 0.f) : v;
        }
#pragma unroll
        for (int k = 0; k < 32; k++) {
            float4 w = Ws4[(kc * 32 + k) * 32 + lane];
#pragma unroll
            for (int j = 0; j < 4; j++) {
                float hv = __shfl_sync(0xffffffffu, h[j], k);
                acc[j].x += hv * w.x;
                acc[j].y += hv * w.y;
                acc[j].z += hv * w.z;
                acc[j].w += hv * w.w;
            }
        }
    }

    float4 bv = ((const float4*)b)[lane];
#pragma unroll
    for (int j = 0; j < 4; j++) {
        int r = row0 + j;
        if (r >= n) break;
        float sc = g_selfc[r];
        ((float4*)T)[(size_t)r * 32 + lane] = acc[j];
        float4 o;
        o.x = acc[j].x * sc + bv.x;
        o.y = acc[j].y * sc + bv.y;
        o.z = acc[j].z * sc + bv.z;
        o.w = acc[j].w * sc + bv.w;
        ((float4*)Hout)[(size_t)r * 32 + lane] = o;
    }
}

// ---------------- edge scatter: Hout[dst] += T[src] * coef ------------------
// One warp per edge; float4 per lane; vector reduction (sm_90+ red.v4.f32).
__global__ void scatter_kernel(const float* __restrict__ T, float* __restrict__ Hout, int E) {
    int e = blockIdx.x * 8 + (threadIdx.x >> 5);
    if (e >= E) return;
    int lane = threadIdx.x & 31;
    int s = g_src[e];
    int d = g_dst[e];
    float c = g_coef[e];
    float4 v = ((const float4*)T)[(size_t)s * 32 + lane];
    float* p = Hout + (size_t)d * 128 + lane * 4;
    asm volatile("red.global.add.v4.f32 [%0], {%1,%2,%3,%4};"
                 :: "l"(p), "f"(v.x * c), "f"(v.y * c), "f"(v.z * c), "f"(v.w * c)
                 : "memory");
}

// ---------------- pool (sorted batch -> block-per-graph) + head -------------
__device__ __forceinline__ long long batch_val(const void* b, int i, int is64) {
    return is64 ? ((const long long*)b)[i] : (long long)((const int*)b)[i];
}
__device__ __forceinline__ int lb_batch(const void* b, int n, int is64, long long key) {
    int lo = 0, hi = n;
    while (lo < hi) {
        int mid = (lo + hi) >> 1;
        if (batch_val(b, mid, is64) < key) lo = mid + 1; else hi = mid;
    }
    return lo;
}

__global__ void pool_kernel(const float* __restrict__ Hf, const void* __restrict__ batch,
                            const float* __restrict__ Wl, const float* __restrict__ bl,
                            float* __restrict__ out, int n) {
    int g = blockIdx.x;
    int is64 = g_batch64;
    int lo = lb_batch(batch, n, is64, (long long)g);
    int hi = lb_batch(batch, n, is64, (long long)g + 1);
    int f = threadIdx.x;

    float sum = 0.f;
    for (int i = lo; i < hi; i++)
        sum += fmaxf(Hf[(size_t)i * 128 + f], 0.f);       // relu fused here

    float cnt = (float)((hi - lo) > 0 ? (hi - lo) : 1);
    __shared__ float sp[128];
    sp[f] = sum / cnt;
    __syncthreads();

    if (f < 5) {
        float a = bl[f];
#pragma unroll 8
        for (int k = 0; k < 128; k++) a += sp[k] * Wl[k * 5 + f];
        out[g * 5 + f] = 1.f / (1.f + expf(-a));
    }
}

// ---------------- launch -----------------------------------------------------
extern "C" void kernel_launch(void* const* d_in, const int* in_sizes, int n_in,
                              void* d_out, int out_size) {
    const float* x  = (const float*)d_in[0];
    const void*  ei = d_in[1];
    const void*  bt = d_in[2];
    const float* W1 = (const float*)d_in[3];
    const float* b1 = (const float*)d_in[4];
    const float* W2 = (const float*)d_in[5];
    const float* b2 = (const float*)d_in[6];
    const float* W3 = (const float*)d_in[7];
    const float* b3 = (const float*)d_in[8];
    const float* W4 = (const float*)d_in[9];
    const float* b4 = (const float*)d_in[10];
    const float* Wl = (const float*)d_in[11];
    const float* bl = (const float*)d_in[12];
    float* out = (float*)d_out;

    int n  = in_sizes[0] / 4;      // nodes
    int E  = in_sizes[1] / 2;      // edges
    int nb = in_sizes[2];          // == n
    int G  = out_size / 5;         // graphs

    float *T, *A, *B;
    cudaGetSymbolAddress((void**)&T, g_T);
    cudaGetSymbolAddress((void**)&A, g_A);
    cudaGetSymbolAddress((void**)&B, g_B);

    cudaFuncSetAttribute(mm128_kernel, cudaFuncAttributeMaxDynamicSharedMemorySize, 64 * 1024);

    const int TB = 256;
    int gN  = (n + TB - 1) / TB;
    int gE  = (E + TB - 1) / TB;
    int gMM = (n + 31) / 32;       // 8 warps * 4 rows per block
    int gSC = (E + 7) / 8;         // 1 warp per edge

    // prep
    detect_kernel<<<1, 1>>>((const int*)ei, (const int*)bt, nb);
    deg_init_kernel<<<gN, TB>>>(n);
    edge_prep_kernel<<<gE, TB>>>(ei, E);
    dinv_kernel<<<gN, TB>>>(n);
    coef_kernel<<<gE, TB>>>(E);

    // layer 1: x -> A
    mm4_kernel<<<(n + 1) / 2, TB>>>(x, W1, b1, T, A, n);
    scatter_kernel<<<gSC, TB>>>(T, A, E);

    // layer 2: relu(A) -> B
    mm128_kernel<<<gMM, TB, 64 * 1024>>>(A, W2, b2, T, B, n, 1);
    scatter_kernel<<<gSC, TB>>>(T, B, E);

    // layer 3: relu(B) -> A
    mm128_kernel<<<gMM, TB, 64 * 1024>>>(B, W3, b3, T, A, n, 1);
    scatter_kernel<<<gSC, TB>>>(T, A, E);

    // layer 4: relu(A) -> B
    mm128_kernel<<<gMM, TB, 64 * 1024>>>(A, W4, b4, T, B, n, 1);
    scatter_kernel<<<gSC, TB>>>(T, B, E);

    // pool (relu fused) + classifier head
    pool_kernel<<<G, 128>>>(B, bt, Wl, bl, out, n);
}

// round 4
// speedup vs baseline: 1.7950x; 1.7950x over previous
#include <cuda_runtime.h>
#include <cstdint>

#define NMAX 100000
#define EMAX 1600000
#define HDIM 128
#define SCAN_B 256
#define NBLK ((NMAX + SCAN_B - 1) / SCAN_B)   // 391

// ---------------- scratch (device globals) ----------------------------------
__device__ float g_T[NMAX * HDIM];     // t = h @ W (pre-aggregation)  (also z[N,4] temp)
__device__ float g_A[NMAX * HDIM];     // ping
__device__ float g_B[NMAX * HDIM];     // pong
__device__ float g_dinv[NMAX];
__device__ float g_selfc[NMAX];        // 1/deg  (self-loop coefficient)
__device__ int   g_count[NMAX];
__device__ int   g_rowptr[NMAX + 1];
__device__ int   g_cursor[NMAX];
__device__ int   g_bsum[512];
__device__ int   g_boff[512];
__device__ int   g_csr_src[EMAX];
__device__ float g_csr_coef[EMAX];
__device__ int   g_edge64;
__device__ int   g_batch64;

// ---------------- dtype detection (int64 vs int32) ---------------------------
__global__ void detect_kernel(const int* __restrict__ ei32,
                              const int* __restrict__ b32, int nb) {
    if (threadIdx.x != 0) return;
    int nz = 0;
#pragma unroll
    for (int i = 1; i < 17; i += 2) nz |= ei32[i];
    g_edge64 = (nz == 0) ? 1 : 0;
    nz = 0;
    for (int k = 0; k < 16; k++) {
        int j = nb - 1 - k;
        if (j >= 1 && (j & 1)) nz |= b32[j];
    }
    g_batch64 = (nz == 0) ? 1 : 0;
}

__device__ __forceinline__ void load_edge(const void* ei, int E, int e, int& s, int& d) {
    if (g_edge64) {
        const long long* p = (const long long*)ei;
        s = (int)p[e]; d = (int)p[E + e];
    } else {
        const int* p = (const int*)ei;
        s = p[e]; d = p[E + e];
    }
}

// ---------------- CSR build --------------------------------------------------
__global__ void count_init_kernel(int n) {
    int i = blockIdx.x * blockDim.x + threadIdx.x;
    if (i < n) g_count[i] = 0;
}

__global__ void count_kernel(const void* __restrict__ ei, int E) {
    int e = blockIdx.x * blockDim.x + threadIdx.x;
    if (e >= E) return;
    int s, d; load_edge(ei, E, e, s, d);
    atomicAdd(&g_count[d], 1);
}

__global__ void dinv_kernel(int n) {
    int i = blockIdx.x * blockDim.x + threadIdx.x;
    if (i >= n) return;
    float deg = (float)(g_count[i] + 1);   // + self-loop
    float dv = rsqrtf(deg);
    g_dinv[i] = dv;
    g_selfc[i] = 1.0f / deg;
}

__global__ void scan_block_kernel(int n) {
    __shared__ int sh[SCAN_B];
    int tid = threadIdx.x;
    int i = blockIdx.x * SCAN_B + tid;
    int v = (i < n) ? g_count[i] : 0;
    sh[tid] = v;
    __syncthreads();
#pragma unroll
    for (int off = 1; off < SCAN_B; off <<= 1) {
        int t = (tid >= off) ? sh[tid - off] : 0;
        __syncthreads();
        sh[tid] += t;
        __syncthreads();
    }
    if (i < n) g_rowptr[i] = sh[tid] - v;           // exclusive within block
    if (tid == SCAN_B - 1) g_bsum[blockIdx.x] = sh[tid];
}

__global__ void scan_top_kernel(int nblk) {
    __shared__ int sh[512];
    int tid = threadIdx.x;
    int v = (tid < nblk) ? g_bsum[tid] : 0;
    sh[tid] = v;
    __syncthreads();
#pragma unroll
    for (int off = 1; off < 512; off <<= 1) {
        int t = (tid >= off) ? sh[tid - off] : 0;
        __syncthreads();
        sh[tid] += t;
        __syncthreads();
    }
    g_boff[tid] = sh[tid] - v;                      // exclusive
}

__global__ void scan_add_kernel(int n, int E) {
    int i = blockIdx.x * blockDim.x + threadIdx.x;
    if (i < n) {
        int r = g_rowptr[i] + g_boff[blockIdx.x * blockDim.x / SCAN_B + (threadIdx.x / SCAN_B)];
        // blockDim == SCAN_B so the index is just blockIdx.x
        r = g_rowptr[i] + g_boff[blockIdx.x];
        g_rowptr[i] = r;
        g_cursor[i] = r;
    }
    if (i == 0) g_rowptr[n] = E;
}

__global__ void fill_kernel(const void* __restrict__ ei, int E) {
    int e = blockIdx.x * blockDim.x + threadIdx.x;
    if (e >= E) return;
    int s, d; load_edge(ei, E, e, s, d);
    float c = g_dinv[s] * g_dinv[d];
    int idx = atomicAdd(&g_cursor[d], 1);
    g_csr_src[idx] = s;
    g_csr_coef[idx] = c;
}

// ---------------- layer 1: z = A_norm x  (4-wide gather) ---------------------
__global__ void agg4_kernel(const float* __restrict__ x, float* __restrict__ z, int n) {
    int i = blockIdx.x * blockDim.x + threadIdx.x;
    if (i >= n) return;
    const float4* x4 = (const float4*)x;
    float4 xv = x4[i];
    float sc = g_selfc[i];
    float4 acc = make_float4(xv.x * sc, xv.y * sc, xv.z * sc, xv.w * sc);
    int lo = g_rowptr[i], hi = g_rowptr[i + 1];
    int e = lo;
    for (; e + 4 <= hi; e += 4) {
        int s0 = g_csr_src[e], s1 = g_csr_src[e+1], s2 = g_csr_src[e+2], s3 = g_csr_src[e+3];
        float c0 = g_csr_coef[e], c1 = g_csr_coef[e+1], c2 = g_csr_coef[e+2], c3 = g_csr_coef[e+3];
        float4 v0 = x4[s0], v1 = x4[s1], v2 = x4[s2], v3 = x4[s3];
        acc.x += c0*v0.x + c1*v1.x + c2*v2.x + c3*v3.x;
        acc.y += c0*v0.y + c1*v1.y + c2*v2.y + c3*v3.y;
        acc.z += c0*v0.z + c1*v1.z + c2*v2.z + c3*v3.z;
        acc.w += c0*v0.w + c1*v1.w + c2*v2.w + c3*v3.w;
    }
    for (; e < hi; e++) {
        float c = g_csr_coef[e];
        float4 v = x4[g_csr_src[e]];
        acc.x += c*v.x; acc.y += c*v.y; acc.z += c*v.z; acc.w += c*v.w;
    }
    ((float4*)z)[i] = acc;
}

// ---------------- layer 1 matmul: H1 = z @ W1 + b1 ---------------------------
__global__ void mm4_kernel(const float* __restrict__ z, const float* __restrict__ W,
                           const float* __restrict__ b, float* __restrict__ Hout, int n) {
    __shared__ float Ws[4 * 128 + 128];
    for (int i = threadIdx.x; i < 512; i += blockDim.x) Ws[i] = W[i];
    for (int i = threadIdx.x; i < 128; i += blockDim.x) Ws[512 + i] = b[i];
    __syncthreads();
    int node = blockIdx.x * 2 + (threadIdx.x >> 7);
    if (node >= n) return;
    int f = threadIdx.x & 127;
    float4 zv = ((const float4*)z)[node];
    float acc = Ws[512 + f] + zv.x * Ws[f] + zv.y * Ws[128 + f]
              + zv.z * Ws[256 + f] + zv.w * Ws[384 + f];
    Hout[(size_t)node * 128 + f] = acc;
}

// ---------------- layers 2..4 matmul: T = relu(Hin) @ W ----------------------
__global__ void mm128_kernel(const float* __restrict__ Hin, const float* __restrict__ W,
                             float* __restrict__ T, int n) {
    extern __shared__ float4 Ws4[];                       // [128][32] float4 = 64KB
    const float4* W4 = (const float4*)W;
    for (int i = threadIdx.x; i < 128 * 32; i += blockDim.x) Ws4[i] = W4[i];
    __syncthreads();

    int warp = threadIdx.x >> 5;
    int lane = threadIdx.x & 31;
    int row0 = (blockIdx.x * 8 + warp) * 4;
    if (row0 >= n) return;

    float4 acc[4];
#pragma unroll
    for (int j = 0; j < 4; j++) acc[j] = make_float4(0.f, 0.f, 0.f, 0.f);

#pragma unroll
    for (int kc = 0; kc < 4; kc++) {
        float h[4];
#pragma unroll
        for (int j = 0; j < 4; j++) {
            int r = row0 + j; if (r >= n) r = n - 1;
            h[j] = fmaxf(Hin[(size_t)r * 128 + kc * 32 + lane], 0.f);
        }
#pragma unroll
        for (int k = 0; k < 32; k++) {
            float4 w = Ws4[(kc * 32 + k) * 32 + lane];
#pragma unroll
            for (int j = 0; j < 4; j++) {
                float hv = __shfl_sync(0xffffffffu, h[j], k);
                acc[j].x += hv * w.x;
                acc[j].y += hv * w.y;
                acc[j].z += hv * w.z;
                acc[j].w += hv * w.w;
            }
        }
    }
#pragma unroll
    for (int j = 0; j < 4; j++) {
        int r = row0 + j;
        if (r >= n) break;
        ((float4*)T)[(size_t)r * 32 + lane] = acc[j];
    }
}

// ---------------- CSR gather: Hout[i] = b + selfc[i]*T[i] + sum coef*T[src] --
__global__ void gather_kernel(const float* __restrict__ T, const float* __restrict__ b,
                              float* __restrict__ Hout, int n) {
    int node = blockIdx.x * 8 + (threadIdx.x >> 5);
    if (node >= n) return;
    int lane = threadIdx.x & 31;
    const float4* T4 = (const float4*)T;

    float4 acc = T4[(size_t)node * 32 + lane];
    float sc = g_selfc[node];
    acc.x *= sc; acc.y *= sc; acc.z *= sc; acc.w *= sc;

    int lo = g_rowptr[node], hi = g_rowptr[node + 1];
    for (int base = lo; base < hi; base += 32) {
        int e = base + lane;
        int s = 0; float c = 0.f;
        if (e < hi) { s = g_csr_src[e]; c = g_csr_coef[e]; }
        int cnt = min(32, hi - base);
        int j = 0;
        for (; j + 4 <= cnt; j += 4) {
            int   s0 = __shfl_sync(0xffffffffu, s, j);
            int   s1 = __shfl_sync(0xffffffffu, s, j + 1);
            int   s2 = __shfl_sync(0xffffffffu, s, j + 2);
            int   s3 = __shfl_sync(0xffffffffu, s, j + 3);
            float c0 = __shfl_sync(0xffffffffu, c, j);
            float c1 = __shfl_sync(0xffffffffu, c, j + 1);
            float c2 = __shfl_sync(0xffffffffu, c, j + 2);
            float c3 = __shfl_sync(0xffffffffu, c, j + 3);
            float4 v0 = T4[(size_t)s0 * 32 + lane];
            float4 v1 = T4[(size_t)s1 * 32 + lane];
            float4 v2 = T4[(size_t)s2 * 32 + lane];
            float4 v3 = T4[(size_t)s3 * 32 + lane];
            acc.x += c0*v0.x + c1*v1.x + c2*v2.x + c3*v3.x;
            acc.y += c0*v0.y + c1*v1.y + c2*v2.y + c3*v3.y;
            acc.z += c0*v0.z + c1*v1.z + c2*v2.z + c3*v3.z;
            acc.w += c0*v0.w + c1*v1.w + c2*v2.w + c3*v3.w;
        }
        for (; j < cnt; j++) {
            int   ss = __shfl_sync(0xffffffffu, s, j);
            float cc = __shfl_sync(0xffffffffu, c, j);
            float4 v = T4[(size_t)ss * 32 + lane];
            acc.x += cc*v.x; acc.y += cc*v.y; acc.z += cc*v.z; acc.w += cc*v.w;
        }
    }
    float4 bv = ((const float4*)b)[lane];
    acc.x += bv.x; acc.y += bv.y; acc.z += bv.z; acc.w += bv.w;
    ((float4*)Hout)[(size_t)node * 32 + lane] = acc;
}

// ---------------- pool + head ------------------------------------------------
__device__ __forceinline__ long long batch_val(const void* b, int i, int is64) {
    return is64 ? ((const long long*)b)[i] : (long long)((const int*)b)[i];
}
__device__ __forceinline__ int lb_batch(const void* b, int n, int is64, long long key) {
    int lo = 0, hi = n;
    while (lo < hi) {
        int mid = (lo + hi) >> 1;
        if (batch_val(b, mid, is64) < key) lo = mid + 1; else hi = mid;
    }
    return lo;
}

__global__ void pool_kernel(const float* __restrict__ Hf, const void* __restrict__ batch,
                            const float* __restrict__ Wl, const float* __restrict__ bl,
                            float* __restrict__ out, int n) {
    int g = blockIdx.x;
    int is64 = g_batch64;
    int lo = lb_batch(batch, n, is64, (long long)g);
    int hi = lb_batch(batch, n, is64, (long long)g + 1);
    int f = threadIdx.x;

    float sum = 0.f;
    for (int i = lo; i < hi; i++)
        sum += fmaxf(Hf[(size_t)i * 128 + f], 0.f);

    float cnt = (float)((hi - lo) > 0 ? (hi - lo) : 1);
    __shared__ float sp[128];
    sp[f] = sum / cnt;
    __syncthreads();

    if (f < 5) {
        float a = bl[f];
#pragma unroll 8
        for (int k = 0; k < 128; k++) a += sp[k] * Wl[k * 5 + f];
        out[g * 5 + f] = 1.f / (1.f + expf(-a));
    }
}

// ---------------- launch -----------------------------------------------------
extern "C" void kernel_launch(void* const* d_in, const int* in_sizes, int n_in,
                              void* d_out, int out_size) {
    const float* x  = (const float*)d_in[0];
    const void*  ei = d_in[1];
    const void*  bt = d_in[2];
    const float* W1 = (const float*)d_in[3];
    const float* b1 = (const float*)d_in[4];
    const float* W2 = (const float*)d_in[5];
    const float* b2 = (const float*)d_in[6];
    const float* W3 = (const float*)d_in[7];
    const float* b3 = (const float*)d_in[8];
    const float* W4 = (const float*)d_in[9];
    const float* b4 = (const float*)d_in[10];
    const float* Wl = (const float*)d_in[11];
    const float* bl = (const float*)d_in[12];
    float* out = (float*)d_out;

    int n  = in_sizes[0] / 4;
    int E  = in_sizes[1] / 2;
    int nb = in_sizes[2];
    int G  = out_size / 5;

    float *T, *A, *B;
    cudaGetSymbolAddress((void**)&T, g_T);
    cudaGetSymbolAddress((void**)&A, g_A);
    cudaGetSymbolAddress((void**)&B, g_B);

    cudaFuncSetAttribute(mm128_kernel, cudaFuncAttributeMaxDynamicSharedMemorySize, 64 * 1024);

    const int TB = 256;
    int gN  = (n + TB - 1) / TB;
    int gE  = (E + TB - 1) / TB;
    int gMM = (n + 31) / 32;
    int gGA = (n + 7) / 8;
    int nblk = (n + SCAN_B - 1) / SCAN_B;

    // prep + CSR build
    detect_kernel<<<1, 32>>>((const int*)ei, (const int*)bt, nb);
    count_init_kernel<<<gN, TB>>>(n);
    count_kernel<<<gE, TB>>>(ei, E);
    dinv_kernel<<<gN, TB>>>(n);
    scan_block_kernel<<<nblk, SCAN_B>>>(n);
    scan_top_kernel<<<1, 512>>>(nblk);
    scan_add_kernel<<<nblk, SCAN_B>>>(n, E);
    fill_kernel<<<gE, TB>>>(ei, E);

    // layer 1: aggregate x first (4-wide), then mm4
    agg4_kernel<<<gN, TB>>>(x, T, n);          // z lives in T temporarily
    mm4_kernel<<<(n + 1) / 2, TB>>>(T, W1, b1, A, n);

    // layers 2..4: mm (relu fused on input) + CSR gather (bias fused)
    mm128_kernel<<<gMM, TB, 64 * 1024>>>(A, W2, T, n);
    gather_kernel<<<gGA, TB>>>(T, b2, B, n);

    mm128_kernel<<<gMM, TB, 64 * 1024>>>(B, W3, T, n);
    gather_kernel<<<gGA, TB>>>(T, b3, A, n);

    mm128_kernel<<<gMM, TB, 64 * 1024>>>(A, W4, T, n);
    gather_kernel<<<gGA, TB>>>(T, b4, B, n);

    // pool (relu fused) + head
    pool_kernel<<<G, 128>>>(B, bt, Wl, bl, out, n);
}

// round 5
// speedup vs baseline: 1.9447x; 1.0834x over previous
#include <cuda_runtime.h>
#include <cstdint>

#define NMAX 100000
#define EMAX 1600000
#define HDIM 128
#define SCAN_B 256

// ---------------- scratch (device globals) ----------------------------------
__device__ float g_T[NMAX * HDIM];     // t = h @ W (pre-aggregation) (also z[N,4] temp)
__device__ float g_A[NMAX * HDIM];     // ping
__device__ float g_B[NMAX * HDIM];     // pong
__device__ float g_dinv[NMAX];
__device__ float g_selfc[NMAX];        // 1/deg (self-loop coefficient)
__device__ int   g_count[NMAX];
__device__ int   g_rowptr[NMAX + 1];
__device__ int   g_cursor[NMAX];
__device__ int   g_bsum[512];
__device__ int   g_boff[512];
__device__ int   g_csr_src[EMAX];
__device__ float g_csr_coef[EMAX];
__device__ unsigned int g_Wp[16384];   // W prepacked into mma B-fragment layout (tf32)
__device__ int   g_edge64;
__device__ int   g_batch64;

// ---------------- dtype detection (int64 vs int32) ---------------------------
__global__ void detect_kernel(const int* __restrict__ ei32,
                              const int* __restrict__ b32, int nb) {
    if (threadIdx.x != 0) return;
    int nz = 0;
#pragma unroll
    for (int i = 1; i < 17; i += 2) nz |= ei32[i];
    g_edge64 = (nz == 0) ? 1 : 0;
    nz = 0;
    for (int k = 0; k < 16; k++) {
        int j = nb - 1 - k;
        if (j >= 1 && (j & 1)) nz |= b32[j];
    }
    g_batch64 = (nz == 0) ? 1 : 0;
}

__device__ __forceinline__ void load_edge(const void* ei, int E, int e, int& s, int& d) {
    if (g_edge64) {
        const long long* p = (const long long*)ei;
        s = (int)p[e]; d = (int)p[E + e];
    } else {
        const int* p = (const int*)ei;
        s = p[e]; d = p[E + e];
    }
}

// ---------------- CSR build --------------------------------------------------
__global__ void count_init_kernel(int n) {
    int i = blockIdx.x * blockDim.x + threadIdx.x;
    if (i < n) g_count[i] = 0;
}

__global__ void count_kernel(const void* __restrict__ ei, int E) {
    int e = blockIdx.x * blockDim.x + threadIdx.x;
    if (e >= E) return;
    int s, d; load_edge(ei, E, e, s, d);
    atomicAdd(&g_count[d], 1);
}

__global__ void dinv_kernel(int n) {
    int i = blockIdx.x * blockDim.x + threadIdx.x;
    if (i >= n) return;
    float deg = (float)(g_count[i] + 1);   // + self-loop
    float dv = rsqrtf(deg);
    g_dinv[i] = dv;
    g_selfc[i] = 1.0f / deg;
}

__global__ void scan_block_kernel(int n) {
    __shared__ int sh[SCAN_B];
    int tid = threadIdx.x;
    int i = blockIdx.x * SCAN_B + tid;
    int v = (i < n) ? g_count[i] : 0;
    sh[tid] = v;
    __syncthreads();
#pragma unroll
    for (int off = 1; off < SCAN_B; off <<= 1) {
        int t = (tid >= off) ? sh[tid - off] : 0;
        __syncthreads();
        sh[tid] += t;
        __syncthreads();
    }
    if (i < n) g_rowptr[i] = sh[tid] - v;
    if (tid == SCAN_B - 1) g_bsum[blockIdx.x] = sh[tid];
}

__global__ void scan_top_kernel(int nblk) {
    __shared__ int sh[512];
    int tid = threadIdx.x;
    int v = (tid < nblk) ? g_bsum[tid] : 0;
    sh[tid] = v;
    __syncthreads();
#pragma unroll
    for (int off = 1; off < 512; off <<= 1) {
        int t = (tid >= off) ? sh[tid - off] : 0;
        __syncthreads();
        sh[tid] += t;
        __syncthreads();
    }
    g_boff[tid] = sh[tid] - v;
}

__global__ void scan_add_kernel(int n, int E) {
    int i = blockIdx.x * blockDim.x + threadIdx.x;
    if (i < n) {
        int r = g_rowptr[i] + g_boff[blockIdx.x];
        g_rowptr[i] = r;
        g_cursor[i] = r;
    }
    if (i == 0) g_rowptr[n] = E;
}

__global__ void fill_kernel(const void* __restrict__ ei, int E) {
    int e = blockIdx.x * blockDim.x + threadIdx.x;
    if (e >= E) return;
    int s, d; load_edge(ei, E, e, s, d);
    float c = g_dinv[s] * g_dinv[d];
    int idx = atomicAdd(&g_cursor[d], 1);
    g_csr_src[idx] = s;
    g_csr_coef[idx] = c;
}

// ---------------- layer 1: z = A_norm x  (4-wide gather) ---------------------
__global__ void agg4_kernel(const float* __restrict__ x, float* __restrict__ z, int n) {
    int i = blockIdx.x * blockDim.x + threadIdx.x;
    if (i >= n) return;
    const float4* x4 = (const float4*)x;
    float4 xv = x4[i];
    float sc = g_selfc[i];
    float4 acc = make_float4(xv.x * sc, xv.y * sc, xv.z * sc, xv.w * sc);
    int lo = g_rowptr[i], hi = g_rowptr[i + 1];
    int e = lo;
    for (; e + 4 <= hi; e += 4) {
        int s0 = g_csr_src[e], s1 = g_csr_src[e+1], s2 = g_csr_src[e+2], s3 = g_csr_src[e+3];
        float c0 = g_csr_coef[e], c1 = g_csr_coef[e+1], c2 = g_csr_coef[e+2], c3 = g_csr_coef[e+3];
        float4 v0 = x4[s0], v1 = x4[s1], v2 = x4[s2], v3 = x4[s3];
        acc.x += c0*v0.x + c1*v1.x + c2*v2.x + c3*v3.x;
        acc.y += c0*v0.y + c1*v1.y + c2*v2.y + c3*v3.y;
        acc.z += c0*v0.z + c1*v1.z + c2*v2.z + c3*v3.z;
        acc.w += c0*v0.w + c1*v1.w + c2*v2.w + c3*v3.w;
    }
    for (; e < hi; e++) {
        float c = g_csr_coef[e];
        float4 v = x4[g_csr_src[e]];
        acc.x += c*v.x; acc.y += c*v.y; acc.z += c*v.z; acc.w += c*v.w;
    }
    ((float4*)z)[i] = acc;
}

// ---------------- layer 1 matmul: H1 = z @ W1 + b1 ---------------------------
__global__ void mm4_kernel(const float* __restrict__ z, const float* __restrict__ W,
                           const float* __restrict__ b, float* __restrict__ Hout, int n) {
    __shared__ float Ws[4 * 128 + 128];
    for (int i = threadIdx.x; i < 512; i += blockDim.x) Ws[i] = W[i];
    for (int i = threadIdx.x; i < 128; i += blockDim.x) Ws[512 + i] = b[i];
    __syncthreads();
    int node = blockIdx.x * 2 + (threadIdx.x >> 7);
    if (node >= n) return;
    int f = threadIdx.x & 127;
    float4 zv = ((const float4*)z)[node];
    float acc = Ws[512 + f] + zv.x * Ws[f] + zv.y * Ws[128 + f]
              + zv.z * Ws[256 + f] + zv.w * Ws[384 + f];
    Hout[(size_t)node * 128 + f] = acc;
}

// ---------------- TF32 helpers -----------------------------------------------
__device__ __forceinline__ unsigned int to_tf32(float f) {
    unsigned int r;
    asm("cvt.rna.tf32.f32 %0, %1;" : "=r"(r) : "f"(f));
    return r;
}

__device__ __forceinline__ void mma_tf32(float& c0, float& c1, float& c2, float& c3,
                                         unsigned int a0, unsigned int a1,
                                         unsigned int a2, unsigned int a3,
                                         unsigned int b0, unsigned int b1) {
    asm volatile("mma.sync.aligned.m16n8k8.row.col.f32.tf32.tf32.f32 "
                 "{%0,%1,%2,%3}, {%4,%5,%6,%7}, {%8,%9}, {%0,%1,%2,%3};"
                 : "+f"(c0), "+f"(c1), "+f"(c2), "+f"(c3)
                 : "r"(a0), "r"(a1), "r"(a2), "r"(a3), "r"(b0), "r"(b1));
}

// ---------------- W prepack into B-fragment layout ---------------------------
// For m16n8k8.row.col: B-frag reg r of thread t = B[k0 + t%4 + 4r][n0 + t/4].
// Packed index: ((kt*4 + wn)*32 + lane)*8 + (ntl*2 + r), so each warp's k-step
// is 2 contiguous LDS.128 per lane.
__global__ void prepack_kernel(const float* __restrict__ W) {
    int idx = blockIdx.x * blockDim.x + threadIdx.x;
    if (idx >= 16384) return;
    int j    = idx & 7;
    int lane = (idx >> 3) & 31;
    int wn   = (idx >> 8) & 3;
    int kt   = idx >> 10;
    int r    = j & 1;
    int ntl  = j >> 1;
    int k    = 8 * kt + (lane & 3) + 4 * r;
    int ncol = wn * 32 + ntl * 8 + (lane >> 2);
    g_Wp[idx] = to_tf32(W[k * 128 + ncol]);
}

// ---------------- layers 2..4 matmul: T = relu(Hin) @ W  (TF32 tensor cores) -
// Block tile 128m x 128n, 8 warps (2m x 4n); warp tile 64m x 32n (4x4 mma tiles).
#define MM_SMEM (128 * 132 * 4 + 16384 * 4)
__global__ void __launch_bounds__(256, 1) mm_tc_kernel(const float* __restrict__ Hin,
                                                       float* __restrict__ T, int n) {
    extern __shared__ float smem[];
    float* As = smem;                                  // [128][132] tf32 bits
    unsigned int* Ws = (unsigned int*)(smem + 128 * 132);
    unsigned int* Asu = (unsigned int*)As;

    int tid = threadIdx.x;
    int row0 = blockIdx.x * 128;

    // stage A: relu + tf32 convert, row pad 132
    {
        float4* As4 = (float4*)As;
        const float4* H4 = (const float4*)Hin;
        for (int i = tid; i < 128 * 32; i += 256) {
            int r = i >> 5;
            int c4 = i & 31;
            int gr = row0 + r;
            float4 v = make_float4(0.f, 0.f, 0.f, 0.f);
            if (gr < n) v = H4[(size_t)gr * 32 + c4];
            float4 o;
            o.x = __uint_as_float(to_tf32(fmaxf(v.x, 0.f)));
            o.y = __uint_as_float(to_tf32(fmaxf(v.y, 0.f)));
            o.z = __uint_as_float(to_tf32(fmaxf(v.z, 0.f)));
            o.w = __uint_as_float(to_tf32(fmaxf(v.w, 0.f)));
            As4[r * 33 + c4] = o;
        }
        // copy prepacked W
        uint4* Wd = (uint4*)Ws;
        const uint4* Wsrc = (const uint4*)g_Wp;
        for (int i = tid; i < 4096; i += 256) Wd[i] = Wsrc[i];
    }
    __syncthreads();

    int warp = tid >> 5;
    int lane = tid & 31;
    int wm = warp >> 2;            // 0..1
    int wn = warp & 3;             // 0..3
    int l4 = lane >> 2;
    int lm4 = lane & 3;

    float acc[4][4][4];
#pragma unroll
    for (int mt = 0; mt < 4; mt++)
#pragma unroll
        for (int nt = 0; nt < 4; nt++)
#pragma unroll
            for (int r = 0; r < 4; r++) acc[mt][nt][r] = 0.f;

    int rowoff[4];
#pragma unroll
    for (int mt = 0; mt < 4; mt++) rowoff[mt] = (wm * 64 + mt * 16 + l4) * 132;

    const uint4* WB = (const uint4*)Ws;
#pragma unroll
    for (int kt = 0; kt < 16; kt++) {
        int col0 = kt * 8 + lm4;
        unsigned int a[4][4];
#pragma unroll
        for (int mt = 0; mt < 4; mt++) {
            a[mt][0] = Asu[rowoff[mt] + col0];
            a[mt][1] = Asu[rowoff[mt] + 8 * 132 + col0];
            a[mt][2] = Asu[rowoff[mt] + col0 + 4];
            a[mt][3] = Asu[rowoff[mt] + 8 * 132 + col0 + 4];
        }
        int wbase = (((kt * 4 + wn) * 32 + lane) * 8) >> 2;
        uint4 w0 = WB[wbase];
        uint4 w1 = WB[wbase + 1];
        unsigned int b[4][2] = {{w0.x, w0.y}, {w0.z, w0.w}, {w1.x, w1.y}, {w1.z, w1.w}};
#pragma unroll
        for (int mt = 0; mt < 4; mt++)
#pragma unroll
            for (int nt = 0; nt < 4; nt++)
                mma_tf32(acc[mt][nt][0], acc[mt][nt][1], acc[mt][nt][2], acc[mt][nt][3],
                         a[mt][0], a[mt][1], a[mt][2], a[mt][3], b[nt][0], b[nt][1]);
    }

    // epilogue: write T
#pragma unroll
    for (int mt = 0; mt < 4; mt++) {
        int row = row0 + wm * 64 + mt * 16 + l4;
#pragma unroll
        for (int nt = 0; nt < 4; nt++) {
            int col = wn * 32 + nt * 8 + 2 * lm4;
            if (row < n)
                *(float2*)&T[(size_t)row * 128 + col] =
                    make_float2(acc[mt][nt][0], acc[mt][nt][1]);
            if (row + 8 < n)
                *(float2*)&T[(size_t)(row + 8) * 128 + col] =
                    make_float2(acc[mt][nt][2], acc[mt][nt][3]);
        }
    }
}

// ---------------- CSR gather: Hout[i] = b + selfc[i]*T[i] + sum coef*T[src] --
__global__ void gather_kernel(const float* __restrict__ T, const float* __restrict__ b,
                              float* __restrict__ Hout, int n) {
    int node = blockIdx.x * 8 + (threadIdx.x >> 5);
    if (node >= n) return;
    int lane = threadIdx.x & 31;
    const float4* T4 = (const float4*)T;

    float4 acc = T4[(size_t)node * 32 + lane];
    float sc = g_selfc[node];
    acc.x *= sc; acc.y *= sc; acc.z *= sc; acc.w *= sc;

    int lo = g_rowptr[node], hi = g_rowptr[node + 1];
    for (int base = lo; base < hi; base += 32) {
        int e = base + lane;
        int s = 0; float c = 0.f;
        if (e < hi) { s = g_csr_src[e]; c = g_csr_coef[e]; }
        int cnt = min(32, hi - base);
        int j = 0;
        for (; j + 4 <= cnt; j += 4) {
            int   s0 = __shfl_sync(0xffffffffu, s, j);
            int   s1 = __shfl_sync(0xffffffffu, s, j + 1);
            int   s2 = __shfl_sync(0xffffffffu, s, j + 2);
            int   s3 = __shfl_sync(0xffffffffu, s, j + 3);
            float c0 = __shfl_sync(0xffffffffu, c, j);
            float c1 = __shfl_sync(0xffffffffu, c, j + 1);
            float c2 = __shfl_sync(0xffffffffu, c, j + 2);
            float c3 = __shfl_sync(0xffffffffu, c, j + 3);
            float4 v0 = T4[(size_t)s0 * 32 + lane];
            float4 v1 = T4[(size_t)s1 * 32 + lane];
            float4 v2 = T4[(size_t)s2 * 32 + lane];
            float4 v3 = T4[(size_t)s3 * 32 + lane];
            acc.x += c0*v0.x + c1*v1.x + c2*v2.x + c3*v3.x;
            acc.y += c0*v0.y + c1*v1.y + c2*v2.y + c3*v3.y;
            acc.z += c0*v0.z + c1*v1.z + c2*v2.z + c3*v3.z;
            acc.w += c0*v0.w + c1*v1.w + c2*v2.w + c3*v3.w;
        }
        for (; j < cnt; j++) {
            int   ss = __shfl_sync(0xffffffffu, s, j);
            float cc = __shfl_sync(0xffffffffu, c, j);
            float4 v = T4[(size_t)ss * 32 + lane];
            acc.x += cc*v.x; acc.y += cc*v.y; acc.z += cc*v.z; acc.w += cc*v.w;
        }
    }
    float4 bv = ((const float4*)b)[lane];
    acc.x += bv.x; acc.y += bv.y; acc.z += bv.z; acc.w += bv.w;
    ((float4*)Hout)[(size_t)node * 32 + lane] = acc;
}

// ---------------- pool + head ------------------------------------------------
__device__ __forceinline__ long long batch_val(const void* b, int i, int is64) {
    return is64 ? ((const long long*)b)[i] : (long long)((const int*)b)[i];
}
__device__ __forceinline__ int lb_batch(const void* b, int n, int is64, long long key) {
    int lo = 0, hi = n;
    while (lo < hi) {
        int mid = (lo + hi) >> 1;
        if (batch_val(b, mid, is64) < key) lo = mid + 1; else hi = mid;
    }
    return lo;
}

__global__ void pool_kernel(const float* __restrict__ Hf, const void* __restrict__ batch,
                            const float* __restrict__ Wl, const float* __restrict__ bl,
                            float* __restrict__ out, int n) {
    int g = blockIdx.x;
    int is64 = g_batch64;
    int lo = lb_batch(batch, n, is64, (long long)g);
    int hi = lb_batch(batch, n, is64, (long long)g + 1);
    int f = threadIdx.x;

    float sum = 0.f;
    for (int i = lo; i < hi; i++)
        sum += fmaxf(Hf[(size_t)i * 128 + f], 0.f);

    float cnt = (float)((hi - lo) > 0 ? (hi - lo) : 1);
    __shared__ float sp[128];
    sp[f] = sum / cnt;
    __syncthreads();

    if (f < 5) {
        float a = bl[f];
#pragma unroll 8
        for (int k = 0; k < 128; k++) a += sp[k] * Wl[k * 5 + f];
        out[g * 5 + f] = 1.f / (1.f + expf(-a));
    }
}

// ---------------- launch -----------------------------------------------------
extern "C" void kernel_launch(void* const* d_in, const int* in_sizes, int n_in,
                              void* d_out, int out_size) {
    const float* x  = (const float*)d_in[0];
    const void*  ei = d_in[1];
    const void*  bt = d_in[2];
    const float* W1 = (const float*)d_in[3];
    const float* b1 = (const float*)d_in[4];
    const float* W2 = (const float*)d_in[5];
    const float* b2 = (const float*)d_in[6];
    const float* W3 = (const float*)d_in[7];
    const float* b3 = (const float*)d_in[8];
    const float* W4 = (const float*)d_in[9];
    const float* b4 = (const float*)d_in[10];
    const float* Wl = (const float*)d_in[11];
    const float* bl = (const float*)d_in[12];
    float* out = (float*)d_out;

    int n  = in_sizes[0] / 4;
    int E  = in_sizes[1] / 2;
    int nb = in_sizes[2];
    int G  = out_size / 5;

    float *T, *A, *B;
    cudaGetSymbolAddress((void**)&T, g_T);
    cudaGetSymbolAddress((void**)&A, g_A);
    cudaGetSymbolAddress((void**)&B, g_B);

    cudaFuncSetAttribute(mm_tc_kernel, cudaFuncAttributeMaxDynamicSharedMemorySize, MM_SMEM);

    const int TB = 256;
    int gN  = (n + TB - 1) / TB;
    int gE  = (E + TB - 1) / TB;
    int gMM = (n + 127) / 128;
    int gGA = (n + 7) / 8;
    int nblk = (n + SCAN_B - 1) / SCAN_B;

    // prep + CSR build
    detect_kernel<<<1, 32>>>((const int*)ei, (const int*)bt, nb);
    count_init_kernel<<<gN, TB>>>(n);
    count_kernel<<<gE, TB>>>(ei, E);
    dinv_kernel<<<gN, TB>>>(n);
    scan_block_kernel<<<nblk, SCAN_B>>>(n);
    scan_top_kernel<<<1, 512>>>(nblk);
    scan_add_kernel<<<nblk, SCAN_B>>>(n, E);
    fill_kernel<<<gE, TB>>>(ei, E);

    // layer 1: aggregate x first (4-wide), then mm4
    agg4_kernel<<<gN, TB>>>(x, T, n);
    mm4_kernel<<<(n + 1) / 2, TB>>>(T, W1, b1, A, n);

    // layers 2..4: tensor-core mm (relu fused on input) + CSR gather (bias fused)
    prepack_kernel<<<64, 256>>>(W2);
    mm_tc_kernel<<<gMM, TB, MM_SMEM>>>(A, T, n);
    gather_kernel<<<gGA, TB>>>(T, b2, B, n);

    prepack_kernel<<<64, 256>>>(W3);
    mm_tc_kernel<<<gMM, TB, MM_SMEM>>>(B, T, n);
    gather_kernel<<<gGA, TB>>>(T, b3, A, n);

    prepack_kernel<<<64, 256>>>(W4);
    mm_tc_kernel<<<gMM, TB, MM_SMEM>>>(A, T, n);
    gather_kernel<<<gGA, TB>>>(T, b4, B, n);

    // pool (relu fused) + head
    pool_kernel<<<G, 128>>>(B, bt, Wl, bl, out, n);
}

// round 6
// speedup vs baseline: 2.5567x; 1.3147x over previous
#include <cuda_runtime.h>
#include <cuda_fp16.h>
#include <cstdint>

#define NMAX 100000
#define EMAX 1600000
#define HDIM 128
#define SCAN_B 256

// ---------------- scratch (device globals) ----------------------------------
__device__ float g_T[NMAX * HDIM];     // fp32 view; also holds fp16 T and z[N,4] temp
__device__ float g_A[NMAX * HDIM];     // ping
__device__ float g_B[NMAX * HDIM];     // pong
__device__ float g_dinv[NMAX];
__device__ float g_selfc[NMAX];        // 1/deg (self-loop coefficient)
__device__ int   g_count[NMAX];
__device__ int   g_rowptr[NMAX + 1];
__device__ int   g_cursor[NMAX];
__device__ int   g_bsum[512];
__device__ int   g_boff[512];
__device__ int2  g_edges[EMAX];        // packed (src, coef-bits)
__device__ unsigned int g_Wph[8192];   // W prepacked into fp16 mma B-fragment layout
__device__ int   g_edge64;
__device__ int   g_batch64;

// ---------------- dtype detection (int64 vs int32) ---------------------------
__global__ void detect_kernel(const int* __restrict__ ei32,
                              const int* __restrict__ b32, int nb) {
    if (threadIdx.x != 0) return;
    int nz = 0;
#pragma unroll
    for (int i = 1; i < 17; i += 2) nz |= ei32[i];
    g_edge64 = (nz == 0) ? 1 : 0;
    nz = 0;
    for (int k = 0; k < 16; k++) {
        int j = nb - 1 - k;
        if (j >= 1 && (j & 1)) nz |= b32[j];
    }
    g_batch64 = (nz == 0) ? 1 : 0;
}

__device__ __forceinline__ void load_edge(const void* ei, int E, int e, int& s, int& d) {
    if (g_edge64) {
        const long long* p = (const long long*)ei;
        s = (int)p[e]; d = (int)p[E + e];
    } else {
        const int* p = (const int*)ei;
        s = p[e]; d = p[E + e];
    }
}

// ---------------- CSR build --------------------------------------------------
__global__ void count_init_kernel(int n) {
    int i = blockIdx.x * blockDim.x + threadIdx.x;
    if (i < n) g_count[i] = 0;
}

__global__ void count_kernel(const void* __restrict__ ei, int E) {
    int e = blockIdx.x * blockDim.x + threadIdx.x;
    if (e >= E) return;
    int s, d; load_edge(ei, E, e, s, d);
    atomicAdd(&g_count[d], 1);
}

__global__ void dinv_kernel(int n) {
    int i = blockIdx.x * blockDim.x + threadIdx.x;
    if (i >= n) return;
    float deg = (float)(g_count[i] + 1);   // + self-loop
    float dv = rsqrtf(deg);
    g_dinv[i] = dv;
    g_selfc[i] = 1.0f / deg;
}

__global__ void scan_block_kernel(int n) {
    __shared__ int sh[SCAN_B];
    int tid = threadIdx.x;
    int i = blockIdx.x * SCAN_B + tid;
    int v = (i < n) ? g_count[i] : 0;
    sh[tid] = v;
    __syncthreads();
#pragma unroll
    for (int off = 1; off < SCAN_B; off <<= 1) {
        int t = (tid >= off) ? sh[tid - off] : 0;
        __syncthreads();
        sh[tid] += t;
        __syncthreads();
    }
    if (i < n) g_rowptr[i] = sh[tid] - v;
    if (tid == SCAN_B - 1) g_bsum[blockIdx.x] = sh[tid];
}

__global__ void scan_top_kernel(int nblk) {
    __shared__ int sh[512];
    int tid = threadIdx.x;
    int v = (tid < nblk) ? g_bsum[tid] : 0;
    sh[tid] = v;
    __syncthreads();
#pragma unroll
    for (int off = 1; off < 512; off <<= 1) {
        int t = (tid >= off) ? sh[tid - off] : 0;
        __syncthreads();
        sh[tid] += t;
        __syncthreads();
    }
    g_boff[tid] = sh[tid] - v;
}

__global__ void scan_add_kernel(int n, int E) {
    int i = blockIdx.x * blockDim.x + threadIdx.x;
    if (i < n) {
        int r = g_rowptr[i] + g_boff[blockIdx.x];
        g_rowptr[i] = r;
        g_cursor[i] = r;
    }
    if (i == 0) g_rowptr[n] = E;
}

__global__ void fill_kernel(const void* __restrict__ ei, int E) {
    int e = blockIdx.x * blockDim.x + threadIdx.x;
    if (e >= E) return;
    int s, d; load_edge(ei, E, e, s, d);
    float c = g_dinv[s] * g_dinv[d];
    int idx = atomicAdd(&g_cursor[d], 1);
    g_edges[idx] = make_int2(s, __float_as_int(c));
}

// ---------------- layer 1: z = A_norm x  (4-wide gather) ---------------------
__global__ void agg4_kernel(const float* __restrict__ x, float* __restrict__ z, int n) {
    int i = blockIdx.x * blockDim.x + threadIdx.x;
    if (i >= n) return;
    const float4* x4 = (const float4*)x;
    float4 xv = x4[i];
    float sc = g_selfc[i];
    float4 acc = make_float4(xv.x * sc, xv.y * sc, xv.z * sc, xv.w * sc);
    int lo = g_rowptr[i], hi = g_rowptr[i + 1];
    int e = lo;
    for (; e + 4 <= hi; e += 4) {
        int2 e0 = g_edges[e], e1 = g_edges[e+1], e2 = g_edges[e+2], e3 = g_edges[e+3];
        float c0 = __int_as_float(e0.y), c1 = __int_as_float(e1.y);
        float c2 = __int_as_float(e2.y), c3 = __int_as_float(e3.y);
        float4 v0 = x4[e0.x], v1 = x4[e1.x], v2 = x4[e2.x], v3 = x4[e3.x];
        acc.x += c0*v0.x + c1*v1.x + c2*v2.x + c3*v3.x;
        acc.y += c0*v0.y + c1*v1.y + c2*v2.y + c3*v3.y;
        acc.z += c0*v0.z + c1*v1.z + c2*v2.z + c3*v3.z;
        acc.w += c0*v0.w + c1*v1.w + c2*v2.w + c3*v3.w;
    }
    for (; e < hi; e++) {
        int2 ed = g_edges[e];
        float c = __int_as_float(ed.y);
        float4 v = x4[ed.x];
        acc.x += c*v.x; acc.y += c*v.y; acc.z += c*v.z; acc.w += c*v.w;
    }
    ((float4*)z)[i] = acc;
}

// ---------------- layer 1 matmul: H1 = z @ W1 + b1 ---------------------------
__global__ void mm4_kernel(const float* __restrict__ z, const float* __restrict__ W,
                           const float* __restrict__ b, float* __restrict__ Hout, int n) {
    __shared__ float Ws[4 * 128 + 128];
    for (int i = threadIdx.x; i < 512; i += blockDim.x) Ws[i] = W[i];
    for (int i = threadIdx.x; i < 128; i += blockDim.x) Ws[512 + i] = b[i];
    __syncthreads();
    int node = blockIdx.x * 2 + (threadIdx.x >> 7);
    if (node >= n) return;
    int f = threadIdx.x & 127;
    float4 zv = ((const float4*)z)[node];
    float acc = Ws[512 + f] + zv.x * Ws[f] + zv.y * Ws[128 + f]
              + zv.z * Ws[256 + f] + zv.w * Ws[384 + f];
    Hout[(size_t)node * 128 + f] = acc;
}

// ---------------- fp16 mma helpers -------------------------------------------
__device__ __forceinline__ void mma_fp16(float& c0, float& c1, float& c2, float& c3,
                                         unsigned a0, unsigned a1, unsigned a2, unsigned a3,
                                         unsigned b0, unsigned b1) {
    asm volatile("mma.sync.aligned.m16n8k16.row.col.f32.f16.f16.f32 "
                 "{%0,%1,%2,%3}, {%4,%5,%6,%7}, {%8,%9}, {%0,%1,%2,%3};"
                 : "+f"(c0), "+f"(c1), "+f"(c2), "+f"(c3)
                 : "r"(a0), "r"(a1), "r"(a2), "r"(a3), "r"(b0), "r"(b1));
}

// ---------------- W prepack into fp16 B-fragment layout ----------------------
// m16n8k16.row.col B frag: reg r of thread t = half2{ B[k0+2*(t%4)+8r][n0+t/4],
//                                                     B[k0+2*(t%4)+8r+1][n0+t/4] }
// Packed uint32 index: ((kt*4 + wn)*32 + lane)*8 + nt*2 + r
//   -> per warp per k-step: 2 contiguous LDS.128 give the 4 n-tiles' B frags.
__global__ void prepack_kernel(const float* __restrict__ W) {
    int idx = blockIdx.x * blockDim.x + threadIdx.x;
    if (idx >= 8192) return;
    int r    = idx & 1;
    int nt   = (idx >> 1) & 3;
    int lane = (idx >> 3) & 31;
    int wn   = (idx >> 8) & 3;
    int kt   = idx >> 10;                  // 0..7
    int k    = 16 * kt + 2 * (lane & 3) + 8 * r;
    int ncol = wn * 32 + nt * 8 + (lane >> 2);
    __half2 h = __floats2half2_rn(W[k * 128 + ncol], W[(k + 1) * 128 + ncol]);
    g_Wph[idx] = *(unsigned*)&h;
}

// ---------------- layers 2..4 matmul: T = relu(Hin) @ W  (fp16 HMMA) ---------
// Block 128m x 128n x 128k, 8 warps (2m x 4n); warp tile 64m x 32n.
// A staged as half[128][136] (ldmatrix conflict-free), W prepacked in smem.
#define MM_SMEM (128 * 136 * 2 + 8192 * 4)
__global__ void __launch_bounds__(256, 2) mm_tc_kernel(const float* __restrict__ Hin,
                                                       __half* __restrict__ T, int n) {
    extern __shared__ char smem[];
    __half* As = (__half*)smem;
    unsigned* Ws = (unsigned*)(smem + 128 * 136 * 2);

    int tid = threadIdx.x;
    int row0 = blockIdx.x * 128;

    // stage A: relu + fp16 convert
    {
        const float4* H4 = (const float4*)Hin;
        for (int i = tid; i < 128 * 32; i += 256) {
            int r = i >> 5;
            int c4 = i & 31;
            int gr = row0 + r;
            float4 v = make_float4(0.f, 0.f, 0.f, 0.f);
            if (gr < n) v = H4[(size_t)gr * 32 + c4];
            __half2 h0 = __floats2half2_rn(fmaxf(v.x, 0.f), fmaxf(v.y, 0.f));
            __half2 h1 = __floats2half2_rn(fmaxf(v.z, 0.f), fmaxf(v.w, 0.f));
            uint2 p;
            p.x = *(unsigned*)&h0;
            p.y = *(unsigned*)&h1;
            *(uint2*)(As + r * 136 + c4 * 4) = p;
        }
        uint4* Wd = (uint4*)Ws;
        const uint4* Wsrc = (const uint4*)g_Wph;
        for (int i = tid; i < 2048; i += 256) Wd[i] = Wsrc[i];
    }
    __syncthreads();

    int warp = tid >> 5;
    int lane = tid & 31;
    int wm = warp >> 2;            // 0..1
    int wn = warp & 3;             // 0..3

    float acc[4][4][4];
#pragma unroll
    for (int mt = 0; mt < 4; mt++)
#pragma unroll
        for (int nt = 0; nt < 4; nt++)
#pragma unroll
            for (int r = 0; r < 4; r++) acc[mt][nt][r] = 0.f;

    // ldmatrix row/col selection for x4 (a0..a3 order: (m,k)=(0,0),(8,0),(0,8),(8,8))
    int arow = lane & 15;
    int acol = (lane >> 4) << 3;

    const uint4* WB = (const uint4*)Ws;
#pragma unroll
    for (int kt = 0; kt < 8; kt++) {
        unsigned a[4][4];
#pragma unroll
        for (int mt = 0; mt < 4; mt++) {
            const __half* p = As + (wm * 64 + mt * 16 + arow) * 136 + kt * 16 + acol;
            unsigned addr = (unsigned)__cvta_generic_to_shared(p);
            asm volatile("ldmatrix.sync.aligned.m8n8.x4.shared.b16 {%0,%1,%2,%3}, [%4];"
                         : "=r"(a[mt][0]), "=r"(a[mt][1]), "=r"(a[mt][2]), "=r"(a[mt][3])
                         : "r"(addr));
        }
        int wbase = (((kt * 4 + wn) * 32 + lane) * 8) >> 2;   // uint4 index
        uint4 w0 = WB[wbase];
        uint4 w1 = WB[wbase + 1];
        unsigned b[4][2] = {{w0.x, w0.y}, {w0.z, w0.w}, {w1.x, w1.y}, {w1.z, w1.w}};
#pragma unroll
        for (int mt = 0; mt < 4; mt++)
#pragma unroll
            for (int nt = 0; nt < 4; nt++)
                mma_fp16(acc[mt][nt][0], acc[mt][nt][1], acc[mt][nt][2], acc[mt][nt][3],
                         a[mt][0], a[mt][1], a[mt][2], a[mt][3], b[nt][0], b[nt][1]);
    }

    // epilogue: convert to half2, write T
    int l4 = lane >> 2;
    int lm4 = lane & 3;
#pragma unroll
    for (int mt = 0; mt < 4; mt++) {
        int row = row0 + wm * 64 + mt * 16 + l4;
#pragma unroll
        for (int nt = 0; nt < 4; nt++) {
            int col = wn * 32 + nt * 8 + 2 * lm4;
            if (row < n) {
                __half2 h = __floats2half2_rn(acc[mt][nt][0], acc[mt][nt][1]);
                *(unsigned*)&T[(size_t)row * 128 + col] = *(unsigned*)&h;
            }
            if (row + 8 < n) {
                __half2 h = __floats2half2_rn(acc[mt][nt][2], acc[mt][nt][3]);
                *(unsigned*)&T[(size_t)(row + 8) * 128 + col] = *(unsigned*)&h;
            }
        }
    }
}

// ---------------- CSR gather (fp16 T): Hout[i]=b+selfc*T[i]+sum coef*T[src] --
__global__ void gather_kernel(const __half* __restrict__ T, const float* __restrict__ b,
                              float* __restrict__ Hout, int n) {
    int node = blockIdx.x * 8 + (threadIdx.x >> 5);
    if (node >= n) return;
    int lane = threadIdx.x & 31;
    const uint2* T2 = (const uint2*)T;       // 4 halves per element; row stride 32

    float4 acc;
    {
        uint2 raw = T2[(size_t)node * 32 + lane];
        float2 f0 = __half22float2(*(__half2*)&raw.x);
        float2 f1 = __half22float2(*(__half2*)&raw.y);
        float sc = g_selfc[node];
        acc = make_float4(f0.x * sc, f0.y * sc, f1.x * sc, f1.y * sc);
    }

    int lo = g_rowptr[node], hi = g_rowptr[node + 1];
    for (int base = lo; base < hi; base += 32) {
        int e = base + lane;
        int s = 0; float c = 0.f;
        if (e < hi) {
            int2 ed = g_edges[e];
            s = ed.x; c = __int_as_float(ed.y);
        }
        int cnt = min(32, hi - base);
        int j = 0;
        for (; j + 4 <= cnt; j += 4) {
            int   s0 = __shfl_sync(0xffffffffu, s, j);
            int   s1 = __shfl_sync(0xffffffffu, s, j + 1);
            int   s2 = __shfl_sync(0xffffffffu, s, j + 2);
            int   s3 = __shfl_sync(0xffffffffu, s, j + 3);
            float c0 = __shfl_sync(0xffffffffu, c, j);
            float c1 = __shfl_sync(0xffffffffu, c, j + 1);
            float c2 = __shfl_sync(0xffffffffu, c, j + 2);
            float c3 = __shfl_sync(0xffffffffu, c, j + 3);
            uint2 r0 = T2[(size_t)s0 * 32 + lane];
            uint2 r1 = T2[(size_t)s1 * 32 + lane];
            uint2 r2 = T2[(size_t)s2 * 32 + lane];
            uint2 r3 = T2[(size_t)s3 * 32 + lane];
            float2 a0 = __half22float2(*(__half2*)&r0.x), b0 = __half22float2(*(__half2*)&r0.y);
            float2 a1 = __half22float2(*(__half2*)&r1.x), b1 = __half22float2(*(__half2*)&r1.y);
            float2 a2 = __half22float2(*(__half2*)&r2.x), b2 = __half22float2(*(__half2*)&r2.y);
            float2 a3 = __half22float2(*(__half2*)&r3.x), b3 = __half22float2(*(__half2*)&r3.y);
            acc.x += c0*a0.x + c1*a1.x + c2*a2.x + c3*a3.x;
            acc.y += c0*a0.y + c1*a1.y + c2*a2.y + c3*a3.y;
            acc.z += c0*b0.x + c1*b1.x + c2*b2.x + c3*b3.x;
            acc.w += c0*b0.y + c1*b1.y + c2*b2.y + c3*b3.y;
        }
        for (; j < cnt; j++) {
            int   ss = __shfl_sync(0xffffffffu, s, j);
            float cc = __shfl_sync(0xffffffffu, c, j);
            uint2 r = T2[(size_t)ss * 32 + lane];
            float2 f0 = __half22float2(*(__half2*)&r.x);
            float2 f1 = __half22float2(*(__half2*)&r.y);
            acc.x += cc*f0.x; acc.y += cc*f0.y; acc.z += cc*f1.x; acc.w += cc*f1.y;
        }
    }
    float4 bv = ((const float4*)b)[lane];
    acc.x += bv.x; acc.y += bv.y; acc.z += bv.z; acc.w += bv.w;
    ((float4*)Hout)[(size_t)node * 32 + lane] = acc;
}

// ---------------- pool + head ------------------------------------------------
__device__ __forceinline__ long long batch_val(const void* b, int i, int is64) {
    return is64 ? ((const long long*)b)[i] : (long long)((const int*)b)[i];
}
__device__ __forceinline__ int lb_batch(const void* b, int n, int is64, long long key) {
    int lo = 0, hi = n;
    while (lo < hi) {
        int mid = (lo + hi) >> 1;
        if (batch_val(b, mid, is64) < key) lo = mid + 1; else hi = mid;
    }
    return lo;
}

__global__ void pool_kernel(const float* __restrict__ Hf, const void* __restrict__ batch,
                            const float* __restrict__ Wl, const float* __restrict__ bl,
                            float* __restrict__ out, int n) {
    int g = blockIdx.x;
    int is64 = g_batch64;
    int lo = lb_batch(batch, n, is64, (long long)g);
    int hi = lb_batch(batch, n, is64, (long long)g + 1);
    int f = threadIdx.x;

    float sum = 0.f;
    for (int i = lo; i < hi; i++)
        sum += fmaxf(Hf[(size_t)i * 128 + f], 0.f);

    float cnt = (float)((hi - lo) > 0 ? (hi - lo) : 1);
    __shared__ float sp[128];
    sp[f] = sum / cnt;
    __syncthreads();

    if (f < 5) {
        float a = bl[f];
#pragma unroll 8
        for (int k = 0; k < 128; k++) a += sp[k] * Wl[k * 5 + f];
        out[g * 5 + f] = 1.f / (1.f + expf(-a));
    }
}

// ---------------- launch -----------------------------------------------------
extern "C" void kernel_launch(void* const* d_in, const int* in_sizes, int n_in,
                              void* d_out, int out_size) {
    const float* x  = (const float*)d_in[0];
    const void*  ei = d_in[1];
    const void*  bt = d_in[2];
    const float* W1 = (const float*)d_in[3];
    const float* b1 = (const float*)d_in[4];
    const float* W2 = (const float*)d_in[5];
    const float* b2 = (const float*)d_in[6];
    const float* W3 = (const float*)d_in[7];
    const float* b3 = (const float*)d_in[8];
    const float* W4 = (const float*)d_in[9];
    const float* b4 = (const float*)d_in[10];
    const float* Wl = (const float*)d_in[11];
    const float* bl = (const float*)d_in[12];
    float* out = (float*)d_out;

    int n  = in_sizes[0] / 4;
    int E  = in_sizes[1] / 2;
    int nb = in_sizes[2];
    int G  = out_size / 5;

    float *Tf, *A, *B;
    cudaGetSymbolAddress((void**)&Tf, g_T);
    cudaGetSymbolAddress((void**)&A, g_A);
    cudaGetSymbolAddress((void**)&B, g_B);
    __half* Th = (__half*)Tf;

    cudaFuncSetAttribute(mm_tc_kernel, cudaFuncAttributeMaxDynamicSharedMemorySize, MM_SMEM);

    const int TB = 256;
    int gN  = (n + TB - 1) / TB;
    int gE  = (E + TB - 1) / TB;
    int gMM = (n + 127) / 128;
    int gGA = (n + 7) / 8;
    int nblk = (n + SCAN_B - 1) / SCAN_B;

    // prep + CSR build
    detect_kernel<<<1, 32>>>((const int*)ei, (const int*)bt, nb);
    count_init_kernel<<<gN, TB>>>(n);
    count_kernel<<<gE, TB>>>(ei, E);
    dinv_kernel<<<gN, TB>>>(n);
    scan_block_kernel<<<nblk, SCAN_B>>>(n);
    scan_top_kernel<<<1, 512>>>(nblk);
    scan_add_kernel<<<nblk, SCAN_B>>>(n, E);
    fill_kernel<<<gE, TB>>>(ei, E);

    // layer 1: aggregate x first (4-wide), then mm4
    agg4_kernel<<<gN, TB>>>(x, Tf, n);          // z lives in T temporarily
    mm4_kernel<<<(n + 1) / 2, TB>>>(Tf, W1, b1, A, n);

    // layers 2..4: fp16 tensor-core mm + fp16 CSR gather
    prepack_kernel<<<32, 256>>>(W2);
    mm_tc_kernel<<<gMM, TB, MM_SMEM>>>(A, Th, n);
    gather_kernel<<<gGA, TB>>>(Th, b2, B, n);

    prepack_kernel<<<32, 256>>>(W3);
    mm_tc_kernel<<<gMM, TB, MM_SMEM>>>(B, Th, n);
    gather_kernel<<<gGA, TB>>>(Th, b3, A, n);

    prepack_kernel<<<32, 256>>>(W4);
    mm_tc_kernel<<<gMM, TB, MM_SMEM>>>(A, Th, n);
    gather_kernel<<<gGA, TB>>>(Th, b4, B, n);

    // pool (relu fused) + head
    pool_kernel<<<G, 128>>>(B, bt, Wl, bl, out, n);
}

// round 7
// speedup vs baseline: 3.0788x; 1.2042x over previous
#include <cuda_runtime.h>
#include <cuda_fp16.h>
#include <cstdint>

#define NMAX 100000
#define EMAX 1600000
#define HDIM 128
#define SCAN_B 256

// ---------------- scratch (device globals) ----------------------------------
__device__ float g_T[NMAX * HDIM];     // fp16 T lives here; also z[N,4] temp (fp32)
__device__ float g_A[NMAX * HDIM];     // fp16 H ping (reused as half*)
__device__ float g_B[NMAX * HDIM];     // fp16 H pong
__device__ float g_dinv[NMAX];
__device__ float g_selfc[NMAX];        // 1/deg (self-loop coefficient)
__device__ int   g_count[NMAX];
__device__ int   g_rowptr[NMAX + 1];
__device__ int   g_cursor[NMAX];
__device__ int   g_bsum[512];
__device__ int   g_boff[512];
__device__ int2  g_edges[EMAX];        // packed (src, coef-bits)
__device__ unsigned int g_Wph[8192];   // W prepacked into fp16 mma B-fragment layout
__device__ int   g_edge64;
__device__ int   g_batch64;

// ---------------- dtype detection (int64 vs int32) ---------------------------
__global__ void detect_kernel(const int* __restrict__ ei32,
                              const int* __restrict__ b32, int nb) {
    if (threadIdx.x != 0) return;
    int nz = 0;
#pragma unroll
    for (int i = 1; i < 17; i += 2) nz |= ei32[i];
    g_edge64 = (nz == 0) ? 1 : 0;
    nz = 0;
    for (int k = 0; k < 16; k++) {
        int j = nb - 1 - k;
        if (j >= 1 && (j & 1)) nz |= b32[j];
    }
    g_batch64 = (nz == 0) ? 1 : 0;
}

__device__ __forceinline__ void load_edge(const void* ei, int E, int e, int& s, int& d) {
    if (g_edge64) {
        const long long* p = (const long long*)ei;
        s = (int)p[e]; d = (int)p[E + e];
    } else {
        const int* p = (const int*)ei;
        s = p[e]; d = p[E + e];
    }
}

// ---------------- CSR build --------------------------------------------------
__global__ void count_init_kernel(int n) {
    int i = blockIdx.x * blockDim.x + threadIdx.x;
    if (i < n) g_count[i] = 0;
}

__global__ void count_kernel(const void* __restrict__ ei, int E) {
    int e = blockIdx.x * blockDim.x + threadIdx.x;
    if (e >= E) return;
    int s, d; load_edge(ei, E, e, s, d);
    atomicAdd(&g_count[d], 1);
}

// block-local exclusive scan of counts; dinv/selfc fused here (reads count anyway)
__global__ void scan_block_kernel(int n) {
    __shared__ int sh[SCAN_B];
    int tid = threadIdx.x;
    int i = blockIdx.x * SCAN_B + tid;
    int v = (i < n) ? g_count[i] : 0;
    if (i < n) {
        float deg = (float)(v + 1);        // + self-loop
        g_dinv[i] = rsqrtf(deg);
        g_selfc[i] = 1.0f / deg;
    }
    sh[tid] = v;
    __syncthreads();
#pragma unroll
    for (int off = 1; off < SCAN_B; off <<= 1) {
        int t = (tid >= off) ? sh[tid - off] : 0;
        __syncthreads();
        sh[tid] += t;
        __syncthreads();
    }
    if (i < n) g_rowptr[i] = sh[tid] - v;
    if (tid == SCAN_B - 1) g_bsum[blockIdx.x] = sh[tid];
}

__global__ void scan_top_kernel(int nblk) {
    __shared__ int sh[512];
    int tid = threadIdx.x;
    int v = (tid < nblk) ? g_bsum[tid] : 0;
    sh[tid] = v;
    __syncthreads();
#pragma unroll
    for (int off = 1; off < 512; off <<= 1) {
        int t = (tid >= off) ? sh[tid - off] : 0;
        __syncthreads();
        sh[tid] += t;
        __syncthreads();
    }
    g_boff[tid] = sh[tid] - v;
}

__global__ void scan_add_kernel(int n, int E) {
    int i = blockIdx.x * blockDim.x + threadIdx.x;
    if (i < n) {
        int r = g_rowptr[i] + g_boff[blockIdx.x];
        g_rowptr[i] = r;
        g_cursor[i] = r;
    }
    if (i == 0) g_rowptr[n] = E;
}

__global__ void fill_kernel(const void* __restrict__ ei, int E) {
    int e = blockIdx.x * blockDim.x + threadIdx.x;
    if (e >= E) return;
    int s, d; load_edge(ei, E, e, s, d);
    float c = g_dinv[s] * g_dinv[d];
    int idx = atomicAdd(&g_cursor[d], 1);
    g_edges[idx] = make_int2(s, __float_as_int(c));
}

// ---------------- layer 1: z = A_norm x  (4-wide gather) ---------------------
__global__ void agg4_kernel(const float* __restrict__ x, float* __restrict__ z, int n) {
    int i = blockIdx.x * blockDim.x + threadIdx.x;
    if (i >= n) return;
    const float4* x4 = (const float4*)x;
    float4 xv = x4[i];
    float sc = g_selfc[i];
    float4 acc = make_float4(xv.x * sc, xv.y * sc, xv.z * sc, xv.w * sc);
    int lo = g_rowptr[i], hi = g_rowptr[i + 1];
    int e = lo;
    for (; e + 4 <= hi; e += 4) {
        int2 e0 = g_edges[e], e1 = g_edges[e+1], e2 = g_edges[e+2], e3 = g_edges[e+3];
        float c0 = __int_as_float(e0.y), c1 = __int_as_float(e1.y);
        float c2 = __int_as_float(e2.y), c3 = __int_as_float(e3.y);
        float4 v0 = x4[e0.x], v1 = x4[e1.x], v2 = x4[e2.x], v3 = x4[e3.x];
        acc.x += c0*v0.x + c1*v1.x + c2*v2.x + c3*v3.x;
        acc.y += c0*v0.y + c1*v1.y + c2*v2.y + c3*v3.y;
        acc.z += c0*v0.z + c1*v1.z + c2*v2.z + c3*v3.z;
        acc.w += c0*v0.w + c1*v1.w + c2*v2.w + c3*v3.w;
    }
    for (; e < hi; e++) {
        int2 ed = g_edges[e];
        float c = __int_as_float(ed.y);
        float4 v = x4[ed.x];
        acc.x += c*v.x; acc.y += c*v.y; acc.z += c*v.z; acc.w += c*v.w;
    }
    ((float4*)z)[i] = acc;
}

// ---------------- layer 1 matmul: H1 = relu(z @ W1 + b1) -> fp16 -------------
__global__ void mm4_kernel(const float* __restrict__ z, const float* __restrict__ W,
                           const float* __restrict__ b, __half* __restrict__ Hout, int n) {
    __shared__ float Ws[4 * 128 + 128];
    for (int i = threadIdx.x; i < 512; i += blockDim.x) Ws[i] = W[i];
    for (int i = threadIdx.x; i < 128; i += blockDim.x) Ws[512 + i] = b[i];
    __syncthreads();
    int node = blockIdx.x * 2 + (threadIdx.x >> 7);
    if (node >= n) return;
    int f = threadIdx.x & 127;
    float4 zv = ((const float4*)z)[node];
    float acc = Ws[512 + f] + zv.x * Ws[f] + zv.y * Ws[128 + f]
              + zv.z * Ws[256 + f] + zv.w * Ws[384 + f];
    Hout[(size_t)node * 128 + f] = __float2half(fmaxf(acc, 0.f));
}

// ---------------- fp16 mma helpers -------------------------------------------
__device__ __forceinline__ void mma_fp16(float& c0, float& c1, float& c2, float& c3,
                                         unsigned a0, unsigned a1, unsigned a2, unsigned a3,
                                         unsigned b0, unsigned b1) {
    asm volatile("mma.sync.aligned.m16n8k16.row.col.f32.f16.f16.f32 "
                 "{%0,%1,%2,%3}, {%4,%5,%6,%7}, {%8,%9}, {%0,%1,%2,%3};"
                 : "+f"(c0), "+f"(c1), "+f"(c2), "+f"(c3)
                 : "r"(a0), "r"(a1), "r"(a2), "r"(a3), "r"(b0), "r"(b1));
}

// ---------------- W prepack into fp16 B-fragment layout ----------------------
__global__ void prepack_kernel(const float* __restrict__ W) {
    int idx = blockIdx.x * blockDim.x + threadIdx.x;
    if (idx >= 8192) return;
    int r    = idx & 1;
    int nt   = (idx >> 1) & 3;
    int lane = (idx >> 3) & 31;
    int wn   = (idx >> 8) & 3;
    int kt   = idx >> 10;                  // 0..7
    int k    = 16 * kt + 2 * (lane & 3) + 8 * r;
    int ncol = wn * 32 + nt * 8 + (lane >> 2);
    __half2 h = __floats2half2_rn(W[k * 128 + ncol], W[(k + 1) * 128 + ncol]);
    g_Wph[idx] = *(unsigned*)&h;
}

// ---------------- layers 2..4 matmul: T = Hin(fp16) @ W  (fp16 HMMA) ---------
// Block 128m x 128n x 128k, 8 warps (2m x 4n); warp tile 64m x 32n.
#define MM_SMEM (128 * 136 * 2 + 8192 * 4)
__global__ void __launch_bounds__(256, 2) mm_tc_kernel(const __half* __restrict__ Hin,
                                                       __half* __restrict__ T, int n) {
    extern __shared__ char smem[];
    __half* As = (__half*)smem;
    unsigned* Ws = (unsigned*)(smem + 128 * 136 * 2);

    int tid = threadIdx.x;
    int row0 = blockIdx.x * 128;

    // stage A: plain fp16 copy (relu already applied upstream), pad 136
    {
        const uint4* H4 = (const uint4*)Hin;        // 16 uint4 per row
        for (int i = tid; i < 128 * 16; i += 256) {
            int r = i >> 4;
            int c = i & 15;
            int gr = row0 + r;
            uint4 v = make_uint4(0u, 0u, 0u, 0u);
            if (gr < n) v = H4[(size_t)gr * 16 + c];
            *(uint4*)(As + r * 136 + c * 8) = v;
        }
        uint4* Wd = (uint4*)Ws;
        const uint4* Wsrc = (const uint4*)g_Wph;
        for (int i = tid; i < 2048; i += 256) Wd[i] = Wsrc[i];
    }
    __syncthreads();

    int warp = tid >> 5;
    int lane = tid & 31;
    int wm = warp >> 2;            // 0..1
    int wn = warp & 3;             // 0..3

    float acc[4][4][4];
#pragma unroll
    for (int mt = 0; mt < 4; mt++)
#pragma unroll
        for (int nt = 0; nt < 4; nt++)
#pragma unroll
            for (int r = 0; r < 4; r++) acc[mt][nt][r] = 0.f;

    int arow = lane & 15;
    int acol = (lane >> 4) << 3;

    const uint4* WB = (const uint4*)Ws;
#pragma unroll
    for (int kt = 0; kt < 8; kt++) {
        unsigned a[4][4];
#pragma unroll
        for (int mt = 0; mt < 4; mt++) {
            const __half* p = As + (wm * 64 + mt * 16 + arow) * 136 + kt * 16 + acol;
            unsigned addr = (unsigned)__cvta_generic_to_shared(p);
            asm volatile("ldmatrix.sync.aligned.m8n8.x4.shared.b16 {%0,%1,%2,%3}, [%4];"
                         : "=r"(a[mt][0]), "=r"(a[mt][1]), "=r"(a[mt][2]), "=r"(a[mt][3])
                         : "r"(addr));
        }
        int wbase = (((kt * 4 + wn) * 32 + lane) * 8) >> 2;   // uint4 index
        uint4 w0 = WB[wbase];
        uint4 w1 = WB[wbase + 1];
        unsigned b[4][2] = {{w0.x, w0.y}, {w0.z, w0.w}, {w1.x, w1.y}, {w1.z, w1.w}};
#pragma unroll
        for (int mt = 0; mt < 4; mt++)
#pragma unroll
            for (int nt = 0; nt < 4; nt++)
                mma_fp16(acc[mt][nt][0], acc[mt][nt][1], acc[mt][nt][2], acc[mt][nt][3],
                         a[mt][0], a[mt][1], a[mt][2], a[mt][3], b[nt][0], b[nt][1]);
    }

    // epilogue: convert to half2, write T
    int l4 = lane >> 2;
    int lm4 = lane & 3;
#pragma unroll
    for (int mt = 0; mt < 4; mt++) {
        int row = row0 + wm * 64 + mt * 16 + l4;
#pragma unroll
        for (int nt = 0; nt < 4; nt++) {
            int col = wn * 32 + nt * 8 + 2 * lm4;
            if (row < n) {
                __half2 h = __floats2half2_rn(acc[mt][nt][0], acc[mt][nt][1]);
                *(unsigned*)&T[(size_t)row * 128 + col] = *(unsigned*)&h;
            }
            if (row + 8 < n) {
                __half2 h = __floats2half2_rn(acc[mt][nt][2], acc[mt][nt][3]);
                *(unsigned*)&T[(size_t)(row + 8) * 128 + col] = *(unsigned*)&h;
            }
        }
    }
}

// ------- CSR gather: Hout[i] = relu(b + selfc*T[i] + sum coef*T[src]) (fp16) -
__global__ void gather_kernel(const __half* __restrict__ T, const float* __restrict__ b,
                              __half* __restrict__ Hout, int n) {
    int node = blockIdx.x * 8 + (threadIdx.x >> 5);
    if (node >= n) return;
    int lane = threadIdx.x & 31;
    const uint2* T2 = (const uint2*)T;       // 4 halves per lane; row stride 32

    float4 acc;
    {
        uint2 raw = T2[(size_t)node * 32 + lane];
        float2 f0 = __half22float2(*(__half2*)&raw.x);
        float2 f1 = __half22float2(*(__half2*)&raw.y);
        float sc = g_selfc[node];
        acc = make_float4(f0.x * sc, f0.y * sc, f1.x * sc, f1.y * sc);
    }

    int lo = g_rowptr[node], hi = g_rowptr[node + 1];
    for (int base = lo; base < hi; base += 32) {
        int e = base + lane;
        int s = 0; float c = 0.f;
        if (e < hi) {
            int2 ed = g_edges[e];
            s = ed.x; c = __int_as_float(ed.y);
        }
        int cnt = min(32, hi - base);
        int j = 0;
        for (; j + 8 <= cnt; j += 8) {
            int   sa[8]; float ca[8]; uint2 rw[8];
#pragma unroll
            for (int q = 0; q < 8; q++) {
                sa[q] = __shfl_sync(0xffffffffu, s, j + q);
                ca[q] = __shfl_sync(0xffffffffu, c, j + q);
            }
#pragma unroll
            for (int q = 0; q < 8; q++) rw[q] = T2[(size_t)sa[q] * 32 + lane];
#pragma unroll
            for (int q = 0; q < 8; q++) {
                float2 f0 = __half22float2(*(__half2*)&rw[q].x);
                float2 f1 = __half22float2(*(__half2*)&rw[q].y);
                acc.x += ca[q] * f0.x; acc.y += ca[q] * f0.y;
                acc.z += ca[q] * f1.x; acc.w += ca[q] * f1.y;
            }
        }
        for (; j + 4 <= cnt; j += 4) {
            int   sa[4]; float ca[4]; uint2 rw[4];
#pragma unroll
            for (int q = 0; q < 4; q++) {
                sa[q] = __shfl_sync(0xffffffffu, s, j + q);
                ca[q] = __shfl_sync(0xffffffffu, c, j + q);
            }
#pragma unroll
            for (int q = 0; q < 4; q++) rw[q] = T2[(size_t)sa[q] * 32 + lane];
#pragma unroll
            for (int q = 0; q < 4; q++) {
                float2 f0 = __half22float2(*(__half2*)&rw[q].x);
                float2 f1 = __half22float2(*(__half2*)&rw[q].y);
                acc.x += ca[q] * f0.x; acc.y += ca[q] * f0.y;
                acc.z += ca[q] * f1.x; acc.w += ca[q] * f1.y;
            }
        }
        for (; j < cnt; j++) {
            int   ss = __shfl_sync(0xffffffffu, s, j);
            float cc = __shfl_sync(0xffffffffu, c, j);
            uint2 r = T2[(size_t)ss * 32 + lane];
            float2 f0 = __half22float2(*(__half2*)&r.x);
            float2 f1 = __half22float2(*(__half2*)&r.y);
            acc.x += cc*f0.x; acc.y += cc*f0.y; acc.z += cc*f1.x; acc.w += cc*f1.y;
        }
    }
    float4 bv = ((const float4*)b)[lane];
    __half2 h0 = __floats2half2_rn(fmaxf(acc.x + bv.x, 0.f), fmaxf(acc.y + bv.y, 0.f));
    __half2 h1 = __floats2half2_rn(fmaxf(acc.z + bv.z, 0.f), fmaxf(acc.w + bv.w, 0.f));
    uint2 o;
    o.x = *(unsigned*)&h0;
    o.y = *(unsigned*)&h1;
    ((uint2*)Hout)[(size_t)node * 32 + lane] = o;
}

// ---------------- pool (fp16 in, relu'd already) + head ----------------------
__device__ __forceinline__ long long batch_val(const void* b, int i, int is64) {
    return is64 ? ((const long long*)b)[i] : (long long)((const int*)b)[i];
}
__device__ __forceinline__ int lb_batch(const void* b, int n, int is64, long long key) {
    int lo = 0, hi = n;
    while (lo < hi) {
        int mid = (lo + hi) >> 1;
        if (batch_val(b, mid, is64) < key) lo = mid + 1; else hi = mid;
    }
    return lo;
}

__global__ void pool_kernel(const __half* __restrict__ Hf, const void* __restrict__ batch,
                            const float* __restrict__ Wl, const float* __restrict__ bl,
                            float* __restrict__ out, int n) {
    int g = blockIdx.x;
    int is64 = g_batch64;
    int lo = lb_batch(batch, n, is64, (long long)g);
    int hi = lb_batch(batch, n, is64, (long long)g + 1);
    int f = threadIdx.x;              // 0..63, handles half2 pair

    float2 sum = make_float2(0.f, 0.f);
    const __half2* H2 = (const __half2*)Hf;
    for (int i = lo; i < hi; i++) {
        float2 v = __half22float2(H2[(size_t)i * 64 + f]);
        sum.x += v.x; sum.y += v.y;
    }

    float cnt = (float)((hi - lo) > 0 ? (hi - lo) : 1);
    __shared__ float sp[128];
    sp[2 * f]     = sum.x / cnt;
    sp[2 * f + 1] = sum.y / cnt;
    __syncthreads();

    if (f < 5) {
        float a = bl[f];
#pragma unroll 8
        for (int k = 0; k < 128; k++) a += sp[k] * Wl[k * 5 + f];
        out[g * 5 + f] = 1.f / (1.f + expf(-a));
    }
}

// ---------------- launch -----------------------------------------------------
extern "C" void kernel_launch(void* const* d_in, const int* in_sizes, int n_in,
                              void* d_out, int out_size) {
    const float* x  = (const float*)d_in[0];
    const void*  ei = d_in[1];
    const void*  bt = d_in[2];
    const float* W1 = (const float*)d_in[3];
    const float* b1 = (const float*)d_in[4];
    const float* W2 = (const float*)d_in[5];
    const float* b2 = (const float*)d_in[6];
    const float* W3 = (const float*)d_in[7];
    const float* b3 = (const float*)d_in[8];
    const float* W4 = (const float*)d_in[9];
    const float* b4 = (const float*)d_in[10];
    const float* Wl = (const float*)d_in[11];
    const float* bl = (const float*)d_in[12];
    float* out = (float*)d_out;

    int n  = in_sizes[0] / 4;
    int E  = in_sizes[1] / 2;
    int nb = in_sizes[2];
    int G  = out_size / 5;

    float *Tf, *Af, *Bf;
    cudaGetSymbolAddress((void**)&Tf, g_T);
    cudaGetSymbolAddress((void**)&Af, g_A);
    cudaGetSymbolAddress((void**)&Bf, g_B);
    __half* Th = (__half*)Tf;
    __half* Ah = (__half*)Af;
    __half* Bh = (__half*)Bf;

    cudaFuncSetAttribute(mm_tc_kernel, cudaFuncAttributeMaxDynamicSharedMemorySize, MM_SMEM);

    const int TB = 256;
    int gN  = (n + TB - 1) / TB;
    int gE  = (E + TB - 1) / TB;
    int gMM = (n + 127) / 128;
    int gGA = (n + 7) / 8;
    int nblk = (n + SCAN_B - 1) / SCAN_B;

    // prep + CSR build (dinv fused into scan_block)
    detect_kernel<<<1, 32>>>((const int*)ei, (const int*)bt, nb);
    count_init_kernel<<<gN, TB>>>(n);
    count_kernel<<<gE, TB>>>(ei, E);
    scan_block_kernel<<<nblk, SCAN_B>>>(n);
    scan_top_kernel<<<1, 512>>>(nblk);
    scan_add_kernel<<<nblk, SCAN_B>>>(n, E);
    fill_kernel<<<gE, TB>>>(ei, E);

    // layer 1: aggregate x first (4-wide), then mm4 -> relu'd fp16 H1
    agg4_kernel<<<gN, TB>>>(x, Tf, n);          // z lives in T temporarily (fp32)
    mm4_kernel<<<(n + 1) / 2, TB>>>(Tf, W1, b1, Ah, n);

    // layers 2..4: fp16 tensor-core mm + fp16 CSR gather (bias+relu fused)
    prepack_kernel<<<32, 256>>>(W2);
    mm_tc_kernel<<<gMM, TB, MM_SMEM>>>(Ah, Th, n);
    gather_kernel<<<gGA, TB>>>(Th, b2, Bh, n);

    prepack_kernel<<<32, 256>>>(W3);
    mm_tc_kernel<<<gMM, TB, MM_SMEM>>>(Bh, Th, n);
    gather_kernel<<<gGA, TB>>>(Th, b3, Ah, n);

    prepack_kernel<<<32, 256>>>(W4);
    mm_tc_kernel<<<gMM, TB, MM_SMEM>>>(Ah, Th, n);
    gather_kernel<<<gGA, TB>>>(Th, b4, Bh, n);

    // pool (mean of relu'd fp16 H) + head
    pool_kernel<<<G, 64>>>(Bh, bt, Wl, bl, out, n);
}